// round 14
// baseline (speedup 1.0000x reference)
#include <cuda_runtime.h>
#include <cuda_bf16.h>
#include <cuda_fp16.h>
#include <math.h>

#define B_      8
#define NSNP    500000
#define NNODE   2000000
#define NG      20000
#define NF      8
#define H1      1024
#define H2      256
#define H3      16
#define BN_EPS  1e-5f

#define G1_KSPLIT 50
#define G1_KCHUNK 400     // 50 * 400 = 20000
#define G1_JTILES 16      // 16 tiles of 64 columns

// ---------------- f32x2 packed helpers (Blackwell) ---------------------------
__device__ __forceinline__ unsigned long long pack_dup(float x) {
    unsigned long long r;
    asm("mov.b64 %0, {%1, %1};" : "=l"(r) : "f"(x));
    return r;
}
__device__ __forceinline__ void fma2(unsigned long long& d,
                                     unsigned long long a,
                                     unsigned long long b) {
    asm("fma.rn.f32x2 %0, %1, %2, %0;" : "+l"(d) : "l"(a), "l"(b));
}
__device__ __forceinline__ float2 unpack2(unsigned long long v) {
    float2 f;
    asm("mov.b64 {%0, %1}, %2;" : "=f"(f.x), "=f"(f.y) : "l"(v));
    return f;
}

// streaming (evict-first) loads for single-use inputs
__device__ __forceinline__ float4 ldcs4(const float4* p) { return __ldcs(p); }
__device__ __forceinline__ int4   ldcs4i(const int4* p)  { return __ldcs(p); }

// ---------------- scratch ----------------------------------------------------
__device__ __half g_scaledh[NSNP * B_];          // [n][b]  8 MB (L2-resident)
__device__ float  g_sample[NG * B_];             // [g][b]  640 KB
__device__ float  g_h1s[B_ * H1];                // summed (pre-BN)
__device__ float  g_h2s[B_ * H2];                // summed (pre-BN)

// pack 8 floats -> 4 half2 -> one 16B store
__device__ __forceinline__ void store_node8(__half* dst,
                                            float a0, float a1, float a2,
                                            float a3, float a4, float a5,
                                            float a6, float a7) {
    __half2 h0 = __floats2half2_rn(a0, a1);
    __half2 h1 = __floats2half2_rn(a2, a3);
    __half2 h2 = __floats2half2_rn(a4, a5);
    __half2 h3 = __floats2half2_rn(a6, a7);
    uint4 u;
    u.x = *reinterpret_cast<unsigned*>(&h0);
    u.y = *reinterpret_cast<unsigned*>(&h1);
    u.z = *reinterpret_cast<unsigned*>(&h2);
    u.w = *reinterpret_cast<unsigned*>(&h3);
    *reinterpret_cast<uint4*>(dst) = u;
}

// ---------------- K1: fused zero(g_sample, g_h1s, g_h2s) + scale -------------
#define SCALE_BLOCKS ((NSNP / 4 + 255) / 256)                          // 489
#define NZERO        ((NG * B_ + B_ * H1 + B_ * H2) / 4)               // 42560
#define ZERO_BLOCKS  ((NZERO + 255) / 256)
__global__ void k_prep(const float* __restrict__ snp,
                       const float* __restrict__ filters) {
    // must not clobber g_h2s/g_sample while previous replay's consumers run
    cudaGridDependencySynchronize();

    if (blockIdx.x >= SCALE_BLOCKS) {
        int i = (blockIdx.x - SCALE_BLOCKS) * blockDim.x + threadIdx.x;
        const int n0 = NG * B_ / 4;
        const int n1 = n0 + B_ * H1 / 4;
        if (i < n0)
            reinterpret_cast<float4*>(g_sample)[i] =
                make_float4(0.f, 0.f, 0.f, 0.f);
        else if (i < n1)
            reinterpret_cast<float4*>(g_h1s)[i - n0] =
                make_float4(0.f, 0.f, 0.f, 0.f);
        else if (i < NZERO)
            reinterpret_cast<float4*>(g_h2s)[i - n1] =
                make_float4(0.f, 0.f, 0.f, 0.f);
        cudaTriggerProgrammaticLaunchCompletion();
        return;
    }
    int q = blockIdx.x * blockDim.x + threadIdx.x;   // float4 index over n
    if (q >= NSNP / 4) { cudaTriggerProgrammaticLaunchCompletion(); return; }
    float4 s = make_float4(0.f, 0.f, 0.f, 0.f);
#pragma unroll
    for (int f = 0; f < NF; f++) {
        float4 v = ldcs4(reinterpret_cast<const float4*>(filters) +
                         (size_t)f * (NSNP / 4) + q);
        s.x += v.x; s.y += v.y; s.z += v.z; s.w += v.w;
    }
    const float inv = 1.0f / NF;
    s.x *= inv; s.y *= inv; s.z *= inv; s.w *= inv;

    float4 sv[NF];
#pragma unroll
    for (int b = 0; b < NF; b++)
        sv[b] = ldcs4(reinterpret_cast<const float4*>(snp) +
                      (size_t)b * (NSNP / 4) + q);

    int n0 = q * 4;
    __half* o = g_scaledh + (size_t)n0 * 8;
    store_node8(o,      sv[0].x * s.x, sv[1].x * s.x, sv[2].x * s.x, sv[3].x * s.x,
                        sv[4].x * s.x, sv[5].x * s.x, sv[6].x * s.x, sv[7].x * s.x);
    store_node8(o + 8,  sv[0].y * s.y, sv[1].y * s.y, sv[2].y * s.y, sv[3].y * s.y,
                        sv[4].y * s.y, sv[5].y * s.y, sv[6].y * s.y, sv[7].y * s.y);
    store_node8(o + 16, sv[0].z * s.z, sv[1].z * s.z, sv[2].z * s.z, sv[3].z * s.z,
                        sv[4].z * s.z, sv[5].z * s.z, sv[6].z * s.z, sv[7].z * s.z);
    store_node8(o + 24, sv[0].w * s.w, sv[1].w * s.w, sv[2].w * s.w, sv[3].w * s.w,
                        sv[4].w * s.w, sv[5].w * s.w, sv[6].w * s.w, sv[7].w * s.w);
    cudaTriggerProgrammaticLaunchCompletion();
}

// ---------------- K2: segmented sum, fp16 gathers, 32 nodes per subgroup -----
#define NODES_PER_SUB 32
#define SEG_NODES 1024      // 2,000,000 % 1024 = 128 (multiple of 128)
__global__ void k_segsum(const int* __restrict__ ids,
                         const int* __restrict__ seg) {
    __shared__ int sids[SEG_NODES];
    __shared__ int sseg[SEG_NODES];
    int t = threadIdx.x;
    long blockBase = (long)blockIdx.x * SEG_NODES;
    long rem = NNODE - blockBase;       // multiple of 128

    // prologue: index staging is independent of k_prep -> overlaps via PDL
    if (t * 4 < rem)
        reinterpret_cast<int4*>(sids)[t] =
            ldcs4i(reinterpret_cast<const int4*>(ids + blockBase) + t);
    if (t * 4 < rem)
        reinterpret_cast<int4*>(sseg)[t] =
            ldcs4i(reinterpret_cast<const int4*>(seg + blockBase) + t);
    __syncthreads();

    cudaGridDependencySynchronize();    // g_scaledh / zeroed g_sample ready

    int w    = t >> 5;
    int lane = t & 31;
    int sub  = lane >> 3;
    int b    = lane & 7;
    int nb   = w * 128 + sub * NODES_PER_SUB;
    if (w * 128 >= rem) { cudaTriggerProgrammaticLaunchCompletion(); return; }

    float v[NODES_PER_SUB];
#pragma unroll
    for (int k = 0; k < NODES_PER_SUB; k++)
        v[k] = __half2float(
            __ldg(g_scaledh + (size_t)sids[nb + k] * 8 + b));

    int cur = sseg[nb];
    float acc = 0.f;
#pragma unroll
    for (int k = 0; k < NODES_PER_SUB; k++) {
        int sgk = sseg[nb + k];
        if (sgk != cur) {
            atomicAdd(&g_sample[(size_t)cur * 8 + b], acc);
            acc = 0.f;
            cur = sgk;
        }
        acc += v[k];
    }
    atomicAdd(&g_sample[(size_t)cur * 8 + b], acc);
    cudaTriggerProgrammaticLaunchCompletion();
}

// ---------------- K3: GEMM1 direct, 800 blocks, packed f32x2 FMAs ------------
// grid = 50 k-splits x 16 j-tiles(64 cols). 8 warps; warp w strides k rows
// {w, w+8, ...} (50 rows); lane owns 2 consecutive cols (LDG.64 of W).
__global__ void k_gemm1(const float* __restrict__ W1) {
    __shared__ __align__(16) float ssamp[G1_KCHUNK][8];   // 12.8 KB
    __shared__ float sred[8][64 * 8];                      // 16 KB
    int bx = blockIdx.x;
    int jt = bx & (G1_JTILES - 1);
    int k0 = (bx >> 4) * G1_KCHUNK;
    int t  = threadIdx.x;
    int w  = t >> 5;
    int lane = t & 31;
    int j0 = jt * 64;

    cudaGridDependencySynchronize();    // g_sample ready

    for (int i = t; i < G1_KCHUNK * 2; i += 256)
        reinterpret_cast<float4*>(ssamp)[i] =
            __ldg(reinterpret_cast<const float4*>(g_sample) + k0 * 2 + i);
    __syncthreads();

    int j = j0 + lane * 2;
    // acc2[bp][c]: batch-pair bp (b=2bp,2bp+1), column c (2 cols)
    unsigned long long acc2[4][2];
#pragma unroll
    for (int bp = 0; bp < 4; bp++) {
        acc2[bp][0] = 0ull;
        acc2[bp][1] = 0ull;
    }

#pragma unroll 5
    for (int r = 0; r < G1_KCHUNK / 8; r++) {
        int row = r * 8 + w;
        float2 wv = __ldg(reinterpret_cast<const float2*>(
            W1 + (size_t)(k0 + row) * H1 + j));
        ulonglong2 p0 = *reinterpret_cast<const ulonglong2*>(&ssamp[row][0]);
        ulonglong2 p1 = *reinterpret_cast<const ulonglong2*>(&ssamp[row][4]);
        unsigned long long sv2[4] = {p0.x, p0.y, p1.x, p1.y};
        unsigned long long wd0 = pack_dup(wv.x);
        unsigned long long wd1 = pack_dup(wv.y);
#pragma unroll
        for (int bp = 0; bp < 4; bp++) {
            fma2(acc2[bp][0], sv2[bp], wd0);
            fma2(acc2[bp][1], sv2[bp], wd1);
        }
    }

    // sred[w][col_local*8 + b]
#pragma unroll
    for (int c = 0; c < 2; c++) {
        int cl = lane * 2 + c;
#pragma unroll
        for (int bp = 0; bp < 4; bp++) {
            float2 f = unpack2(acc2[bp][c]);
            sred[w][cl * 8 + bp * 2 + 0] = f.x;
            sred[w][cl * 8 + bp * 2 + 1] = f.y;
        }
    }
    __syncthreads();

    // 512 outputs; thread t reduces outputs t and t+256
#pragma unroll
    for (int o = 0; o < 2; o++) {
        int idx = t + o * 256;          // col_local*8 + b
        int cl  = idx >> 3;
        int b_o = idx & 7;
        float tot = sred[0][idx];
#pragma unroll
        for (int x = 1; x < 8; x++)
            tot += sred[x][idx];
        atomicAdd(&g_h1s[b_o * H1 + j0 + cl], tot);
    }
    cudaTriggerProgrammaticLaunchCompletion();
}

// ---------------- K4: GEMM2 direct, W2 prefetched (PDL prologue) -------------
__global__ void k_gemm2(const float* __restrict__ W2,
                        const float* __restrict__ b1,
                        const float* __restrict__ g1,
                        const float* __restrict__ be1) {
    __shared__ float sh[32][8];         // BN1(h1) for this k-chunk
    __shared__ float sred[8][32 * 8];   // per-warp partials
    int bx = blockIdx.x;
    int js = bx & 7;
    int ks = bx >> 3;
    int k0 = ks * 32;
    int j0 = js * 32;
    int t  = threadIdx.x;
    int w  = t >> 5;
    int lane = t & 31;

    // prologue: W2 + BN params, independent of gemm1 output
    float wpre[4];
#pragma unroll
    for (int r = 0; r < 4; r++)
        wpre[r] = __ldg(W2 + (size_t)(k0 + w * 4 + r) * H2 + j0 + lane);
    int kk = k0 + (t >> 3);
    float sc  = g1[kk] * rsqrtf(1.0f + BN_EPS);
    float bb1 = b1[kk];
    float bbe = be1[kk];

    cudaGridDependencySynchronize();    // g_h1s ready

    {
        int b = t & 7;
        float v = (g_h1s[b * H1 + kk] + bb1) * sc + bbe;
        sh[t >> 3][b] = fmaxf(v, 0.f);
    }
    __syncthreads();

    float acc[8];
#pragma unroll
    for (int b = 0; b < 8; b++) acc[b] = 0.f;
#pragma unroll
    for (int r = 0; r < 4; r++) {
        int row = w * 4 + r;
#pragma unroll
        for (int b = 0; b < 8; b++)
            acc[b] = fmaf(sh[row][b], wpre[r], acc[b]);
    }
#pragma unroll
    for (int b = 0; b < 8; b++)
        sred[w][lane * 8 + b] = acc[b];
    __syncthreads();

    int lane_o = t >> 3;
    int b_o    = t & 7;
    float tot = sred[0][lane_o * 8 + b_o];
#pragma unroll
    for (int x = 1; x < 8; x++)
        tot += sred[x][lane_o * 8 + b_o];
    atomicAdd(&g_h2s[b_o * H2 + j0 + lane_o], tot);
    cudaTriggerProgrammaticLaunchCompletion();
}

// ---------------- K5: BN2+ReLU -> GEMM3 -> BN+ReLU -> head -> logits ---------
__global__ void k_final(const float* __restrict__ b2,
                        const float* __restrict__ g2,
                        const float* __restrict__ be2,
                        const float* __restrict__ W3,
                        const float* __restrict__ b3,
                        const float* __restrict__ g3,
                        const float* __restrict__ be3,
                        const float* __restrict__ Wh1,
                        const float* __restrict__ bh1,
                        const float* __restrict__ gh,
                        const float* __restrict__ beh,
                        const float* __restrict__ Wh2,
                        const float* __restrict__ bh2,
                        float* __restrict__ out) {
    __shared__ float sh2[B_ * H2];                 // 8 KB
    __shared__ __align__(16) float sW3[H2 * H3];   // 16 KB
    __shared__ float spart[2][B_ * H3];
    __shared__ float sfeat[B_ * H3];
    int t = threadIdx.x;
    float sbn = rsqrtf(1.0f + BN_EPS);

    // prologue: W3 prefetch, independent of gemm2 output
    float4 w3r[4];
#pragma unroll
    for (int i = 0; i < 4; i++)
        w3r[i] = __ldg(reinterpret_cast<const float4*>(W3) + t * 4 + i);
#pragma unroll
    for (int i = 0; i < 4; i++)
        reinterpret_cast<float4*>(sW3)[t * 4 + i] = w3r[i];

    cudaGridDependencySynchronize();    // g_h2s ready

    // Stage A: BN2 + ReLU from summed h2 (vectorized)
#pragma unroll
    for (int it = 0; it < 2; it++) {
        int i4 = t + it * 256;      // float4 index, 512 total
        float4 v = *reinterpret_cast<const float4*>(g_h2s + i4 * 4);
        float r[4] = {v.x, v.y, v.z, v.w};
#pragma unroll
        for (int c = 0; c < 4; c++) {
            int j = (i4 * 4 + c) & (H2 - 1);
            r[c] = fmaxf((r[c] + b2[j]) * (g2[j] * sbn) + be2[j], 0.f);
        }
        *reinterpret_cast<float4*>(sh2 + i4 * 4) =
            make_float4(r[0], r[1], r[2], r[3]);
    }
    __syncthreads();

    // Stage B: 2-way k-split GEMM3 (W3 from shared)
    {
        int pair = t & 127;
        int half = t >> 7;
        int b = pair >> 4, j = pair & 15;
        float acc = 0.f;
        int kk0 = half * (H2 / 2);
        for (int k = kk0; k < kk0 + H2 / 2; k++)
            acc = fmaf(sh2[b * H2 + k], sW3[k * H3 + j], acc);
        spart[half][pair] = acc;
    }
    __syncthreads();
    if (t < B_ * H3) {
        int j = t & 15;
        float acc = spart[0][t] + spart[1][t];
        float v = (acc + b3[j]) * (g3[j] * sbn) + be3[j];
        sfeat[t] = fmaxf(v, 0.f);
    }
    __syncthreads();

    // Stage C: head
    if (t < B_) {
        int b = t;
        float logit = bh2[0];
#pragma unroll
        for (int q = 0; q < 4; q++) {
            float acc = bh1[q];
            for (int p = 0; p < 15; p++)
                acc = fmaf(sfeat[b * H3 + p], Wh1[p * 4 + q], acc);
            float m = fmaxf(acc * (gh[q] * sbn) + beh[q], 0.f);
            logit = fmaf(m, Wh2[q], logit);
        }
        out[b] = logit;
    }
    cudaTriggerProgrammaticLaunchCompletion();
}

// ---------------- PDL launch helper -------------------------------------------
template <typename F, typename... Args>
static void launch_pdl(F func, int grid, int block, Args... args) {
    cudaLaunchConfig_t cfg = {};
    cfg.gridDim  = dim3(grid, 1, 1);
    cfg.blockDim = dim3(block, 1, 1);
    cfg.stream   = 0;
    cudaLaunchAttribute attr[1];
    attr[0].id = cudaLaunchAttributeProgrammaticStreamSerialization;
    attr[0].val.programmaticStreamSerializationAllowed = 1;
    cfg.attrs = attr;
    cfg.numAttrs = 1;
    cudaLaunchKernelEx(&cfg, func, args...);
}

// ---------------- launch -----------------------------------------------------
extern "C" void kernel_launch(void* const* d_in, const int* in_sizes, int n_in,
                              void* d_out, int out_size) {
    const float* snp      = (const float*)d_in[0];
    const int*   snp_ids  = (const int*)  d_in[1];
    const int*   node_seg = (const int*)  d_in[2];
    const float* filters  = (const float*)d_in[3];
    const float* W1  = (const float*)d_in[4];
    const float* b1  = (const float*)d_in[5];
    const float* g1  = (const float*)d_in[6];
    const float* be1 = (const float*)d_in[7];
    const float* W2  = (const float*)d_in[8];
    const float* b2  = (const float*)d_in[9];
    const float* g2  = (const float*)d_in[10];
    const float* be2 = (const float*)d_in[11];
    const float* W3  = (const float*)d_in[12];
    const float* b3  = (const float*)d_in[13];
    const float* g3  = (const float*)d_in[14];
    const float* be3 = (const float*)d_in[15];
    const float* Wh1 = (const float*)d_in[16];
    const float* bh1 = (const float*)d_in[17];
    const float* gh  = (const float*)d_in[18];
    const float* beh = (const float*)d_in[19];
    const float* Wh2 = (const float*)d_in[20];
    const float* bh2 = (const float*)d_in[21];
    float* out = (float*)d_out;

    int segsum_blocks = (int)((NNODE + SEG_NODES - 1) / SEG_NODES);  // 1954
    launch_pdl(k_prep, SCALE_BLOCKS + ZERO_BLOCKS, 256, snp, filters);
    launch_pdl(k_segsum, segsum_blocks, 256, snp_ids, node_seg);
    launch_pdl(k_gemm1, G1_KSPLIT * G1_JTILES, 256, W1);
    launch_pdl(k_gemm2, 256, 256, W2, b1, g1, be1);
    launch_pdl(k_final, 1, 256, b2, g2, be2, W3, b3, g3, be3,
               Wh1, bh1, gh, beh, Wh2, bh2, out);
}

// round 15
// speedup vs baseline: 1.0423x; 1.0423x over previous
#include <cuda_runtime.h>
#include <cuda_bf16.h>
#include <cuda_fp16.h>
#include <math.h>

#define B_      8
#define NSNP    500000
#define NNODE   2000000
#define NG      20000
#define NF      8
#define H1      1024
#define H2      256
#define H3      16
#define BN_EPS  1e-5f

#define G1_KSPLIT 50
#define G1_KCHUNK 400     // 50 * 400 = 20000

// ---------------- f32x2 packed helpers (Blackwell) ---------------------------
__device__ __forceinline__ unsigned long long pack_dup(float x) {
    unsigned long long r;
    asm("mov.b64 %0, {%1, %1};" : "=l"(r) : "f"(x));
    return r;
}
__device__ __forceinline__ void fma2(unsigned long long& d,
                                     unsigned long long a,
                                     unsigned long long b) {
    asm("fma.rn.f32x2 %0, %1, %2, %0;" : "+l"(d) : "l"(a), "l"(b));
}
__device__ __forceinline__ float2 unpack2(unsigned long long v) {
    float2 f;
    asm("mov.b64 {%0, %1}, %2;" : "=f"(f.x), "=f"(f.y) : "l"(v));
    return f;
}

// streaming (evict-first) loads for single-use inputs
__device__ __forceinline__ float4 ldcs4(const float4* p) { return __ldcs(p); }
__device__ __forceinline__ int4   ldcs4i(const int4* p)  { return __ldcs(p); }

// ---------------- scratch ----------------------------------------------------
__device__ __half g_scaledh[NSNP * B_];          // [n][b]  8 MB (L2-resident)
__device__ float  g_sample[NG * B_];             // [g][b]  640 KB
__device__ float  g_h1s[B_ * H1];                // summed (pre-BN)
__device__ float  g_h2s[B_ * H2];                // summed (pre-BN)

// pack 8 floats -> 4 half2 -> one 16B store
__device__ __forceinline__ void store_node8(__half* dst,
                                            float a0, float a1, float a2,
                                            float a3, float a4, float a5,
                                            float a6, float a7) {
    __half2 h0 = __floats2half2_rn(a0, a1);
    __half2 h1 = __floats2half2_rn(a2, a3);
    __half2 h2 = __floats2half2_rn(a4, a5);
    __half2 h3 = __floats2half2_rn(a6, a7);
    uint4 u;
    u.x = *reinterpret_cast<unsigned*>(&h0);
    u.y = *reinterpret_cast<unsigned*>(&h1);
    u.z = *reinterpret_cast<unsigned*>(&h2);
    u.w = *reinterpret_cast<unsigned*>(&h3);
    *reinterpret_cast<uint4*>(dst) = u;
}

// ---------------- K1: fused zero(g_sample, g_h1s, g_h2s) + scale -------------
#define SCALE_BLOCKS ((NSNP / 4 + 255) / 256)                          // 489
#define NZERO        ((NG * B_ + B_ * H1 + B_ * H2) / 4)               // 42560
#define ZERO_BLOCKS  ((NZERO + 255) / 256)
__global__ void k_prep(const float* __restrict__ snp,
                       const float* __restrict__ filters) {
    // must not clobber g_h2s/g_sample while previous replay's consumers run
    cudaGridDependencySynchronize();

    if (blockIdx.x >= SCALE_BLOCKS) {
        int i = (blockIdx.x - SCALE_BLOCKS) * blockDim.x + threadIdx.x;
        const int n0 = NG * B_ / 4;
        const int n1 = n0 + B_ * H1 / 4;
        if (i < n0)
            reinterpret_cast<float4*>(g_sample)[i] =
                make_float4(0.f, 0.f, 0.f, 0.f);
        else if (i < n1)
            reinterpret_cast<float4*>(g_h1s)[i - n0] =
                make_float4(0.f, 0.f, 0.f, 0.f);
        else if (i < NZERO)
            reinterpret_cast<float4*>(g_h2s)[i - n1] =
                make_float4(0.f, 0.f, 0.f, 0.f);
        cudaTriggerProgrammaticLaunchCompletion();
        return;
    }
    int q = blockIdx.x * blockDim.x + threadIdx.x;   // float4 index over n
    if (q >= NSNP / 4) { cudaTriggerProgrammaticLaunchCompletion(); return; }
    float4 s = make_float4(0.f, 0.f, 0.f, 0.f);
#pragma unroll
    for (int f = 0; f < NF; f++) {
        float4 v = ldcs4(reinterpret_cast<const float4*>(filters) +
                         (size_t)f * (NSNP / 4) + q);
        s.x += v.x; s.y += v.y; s.z += v.z; s.w += v.w;
    }
    const float inv = 1.0f / NF;
    s.x *= inv; s.y *= inv; s.z *= inv; s.w *= inv;

    float4 sv[NF];
#pragma unroll
    for (int b = 0; b < NF; b++)
        sv[b] = ldcs4(reinterpret_cast<const float4*>(snp) +
                      (size_t)b * (NSNP / 4) + q);

    int n0 = q * 4;
    __half* o = g_scaledh + (size_t)n0 * 8;
    store_node8(o,      sv[0].x * s.x, sv[1].x * s.x, sv[2].x * s.x, sv[3].x * s.x,
                        sv[4].x * s.x, sv[5].x * s.x, sv[6].x * s.x, sv[7].x * s.x);
    store_node8(o + 8,  sv[0].y * s.y, sv[1].y * s.y, sv[2].y * s.y, sv[3].y * s.y,
                        sv[4].y * s.y, sv[5].y * s.y, sv[6].y * s.y, sv[7].y * s.y);
    store_node8(o + 16, sv[0].z * s.z, sv[1].z * s.z, sv[2].z * s.z, sv[3].z * s.z,
                        sv[4].z * s.z, sv[5].z * s.z, sv[6].z * s.z, sv[7].z * s.z);
    store_node8(o + 24, sv[0].w * s.w, sv[1].w * s.w, sv[2].w * s.w, sv[3].w * s.w,
                        sv[4].w * s.w, sv[5].w * s.w, sv[6].w * s.w, sv[7].w * s.w);
    cudaTriggerProgrammaticLaunchCompletion();
}

// ---------------- K2: segmented sum, fp16 gathers, 32 nodes per subgroup -----
#define NODES_PER_SUB 32
#define SEG_NODES 1024      // 2,000,000 % 1024 = 128 (multiple of 128)
__global__ void k_segsum(const int* __restrict__ ids,
                         const int* __restrict__ seg) {
    __shared__ int sids[SEG_NODES];
    __shared__ int sseg[SEG_NODES];
    int t = threadIdx.x;
    long blockBase = (long)blockIdx.x * SEG_NODES;
    long rem = NNODE - blockBase;       // multiple of 128

    // prologue: index staging is independent of k_prep -> overlaps via PDL
    if (t * 4 < rem)
        reinterpret_cast<int4*>(sids)[t] =
            ldcs4i(reinterpret_cast<const int4*>(ids + blockBase) + t);
    if (t * 4 < rem)
        reinterpret_cast<int4*>(sseg)[t] =
            ldcs4i(reinterpret_cast<const int4*>(seg + blockBase) + t);
    __syncthreads();

    cudaGridDependencySynchronize();    // g_scaledh / zeroed g_sample ready

    int w    = t >> 5;
    int lane = t & 31;
    int sub  = lane >> 3;
    int b    = lane & 7;
    int nb   = w * 128 + sub * NODES_PER_SUB;
    if (w * 128 >= rem) { cudaTriggerProgrammaticLaunchCompletion(); return; }

    float v[NODES_PER_SUB];
#pragma unroll
    for (int k = 0; k < NODES_PER_SUB; k++)
        v[k] = __half2float(
            __ldg(g_scaledh + (size_t)sids[nb + k] * 8 + b));

    int cur = sseg[nb];
    float acc = 0.f;
#pragma unroll
    for (int k = 0; k < NODES_PER_SUB; k++) {
        int sgk = sseg[nb + k];
        if (sgk != cur) {
            atomicAdd(&g_sample[(size_t)cur * 8 + b], acc);
            acc = 0.f;
            cur = sgk;
        }
        acc += v[k];
    }
    atomicAdd(&g_sample[(size_t)cur * 8 + b], acc);
    cudaTriggerProgrammaticLaunchCompletion();
}

// ---------------- K3: GEMM1 direct (R13 shape) + early W1 prefetch -----------
// grid = 50 k-splits x 8 j-tiles(128 cols). 8 warps; warp w strides k rows
// {w, w+8, ...} (50 rows); lane owns 4 consecutive cols (LDG.128 of W).
__global__ void k_gemm1(const float* __restrict__ W1) {
    __shared__ __align__(16) float ssamp[G1_KCHUNK][8];   // 12.8 KB
    __shared__ float4 sred[8][256];                        // 32 KB
    int bx = blockIdx.x;
    int jt = bx & 7;
    int k0 = (bx >> 3) * G1_KCHUNK;
    int t  = threadIdx.x;
    int w  = t >> 5;
    int lane = t & 31;
    int j0 = jt * 128;
    int j = j0 + lane * 4;

    // early W1 prefetch: inputs have no dependency, overlap the PDL wait
    float4 wpre0 = __ldg(reinterpret_cast<const float4*>(
        W1 + (size_t)(k0 + w) * H1 + j));
    float4 wpre1 = __ldg(reinterpret_cast<const float4*>(
        W1 + (size_t)(k0 + 8 + w) * H1 + j));

    cudaGridDependencySynchronize();    // g_sample ready

    for (int i = t; i < G1_KCHUNK * 2; i += 256)
        reinterpret_cast<float4*>(ssamp)[i] =
            __ldg(reinterpret_cast<const float4*>(g_sample) + k0 * 2 + i);
    __syncthreads();

    unsigned long long acc2[4][4];
#pragma unroll
    for (int bp = 0; bp < 4; bp++)
#pragma unroll
        for (int c = 0; c < 4; c++) acc2[bp][c] = 0ull;

#pragma unroll 5
    for (int r = 0; r < G1_KCHUNK / 8; r++) {
        int row = r * 8 + w;
        float4 wv;
        if (r == 0)      wv = wpre0;
        else if (r == 1) wv = wpre1;
        else             wv = __ldg(reinterpret_cast<const float4*>(
                                  W1 + (size_t)(k0 + row) * H1 + j));
        ulonglong2 p0 = *reinterpret_cast<const ulonglong2*>(&ssamp[row][0]);
        ulonglong2 p1 = *reinterpret_cast<const ulonglong2*>(&ssamp[row][4]);
        unsigned long long sv2[4] = {p0.x, p0.y, p1.x, p1.y};
        unsigned long long wd[4] = {pack_dup(wv.x), pack_dup(wv.y),
                                    pack_dup(wv.z), pack_dup(wv.w)};
#pragma unroll
        for (int bp = 0; bp < 4; bp++) {
            fma2(acc2[bp][0], sv2[bp], wd[0]);
            fma2(acc2[bp][1], sv2[bp], wd[1]);
            fma2(acc2[bp][2], sv2[bp], wd[2]);
            fma2(acc2[bp][3], sv2[bp], wd[3]);
        }
    }

#pragma unroll
    for (int bp = 0; bp < 4; bp++) {
        float2 c0 = unpack2(acc2[bp][0]);
        float2 c1 = unpack2(acc2[bp][1]);
        float2 c2 = unpack2(acc2[bp][2]);
        float2 c3 = unpack2(acc2[bp][3]);
        sred[w][lane * 8 + bp * 2 + 0] = make_float4(c0.x, c1.x, c2.x, c3.x);
        sred[w][lane * 8 + bp * 2 + 1] = make_float4(c0.y, c1.y, c2.y, c3.y);
    }
    __syncthreads();

    int lane_o = t >> 3;
    int b_o    = t & 7;
    float4 tot = sred[0][lane_o * 8 + b_o];
#pragma unroll
    for (int x = 1; x < 8; x++) {
        float4 v = sred[x][lane_o * 8 + b_o];
        tot.x += v.x; tot.y += v.y; tot.z += v.z; tot.w += v.w;
    }
    float* dst = g_h1s + b_o * H1 + j0 + lane_o * 4;
    atomicAdd(dst + 0, tot.x);
    atomicAdd(dst + 1, tot.y);
    atomicAdd(dst + 2, tot.z);
    atomicAdd(dst + 3, tot.w);
    cudaTriggerProgrammaticLaunchCompletion();
}

// ---------------- K4: GEMM2 direct, W2 prefetched (PDL prologue) -------------
__global__ void k_gemm2(const float* __restrict__ W2,
                        const float* __restrict__ b1,
                        const float* __restrict__ g1,
                        const float* __restrict__ be1) {
    __shared__ float sh[32][8];         // BN1(h1) for this k-chunk
    __shared__ float sred[8][32 * 8];   // per-warp partials
    int bx = blockIdx.x;
    int js = bx & 7;
    int ks = bx >> 3;
    int k0 = ks * 32;
    int j0 = js * 32;
    int t  = threadIdx.x;
    int w  = t >> 5;
    int lane = t & 31;

    // prologue: W2 + BN params, independent of gemm1 output
    float wpre[4];
#pragma unroll
    for (int r = 0; r < 4; r++)
        wpre[r] = __ldg(W2 + (size_t)(k0 + w * 4 + r) * H2 + j0 + lane);
    int kk = k0 + (t >> 3);
    float sc  = g1[kk] * rsqrtf(1.0f + BN_EPS);
    float bb1 = b1[kk];
    float bbe = be1[kk];

    cudaGridDependencySynchronize();    // g_h1s ready

    {
        int b = t & 7;
        float v = (g_h1s[b * H1 + kk] + bb1) * sc + bbe;
        sh[t >> 3][b] = fmaxf(v, 0.f);
    }
    __syncthreads();

    float acc[8];
#pragma unroll
    for (int b = 0; b < 8; b++) acc[b] = 0.f;
#pragma unroll
    for (int r = 0; r < 4; r++) {
        int row = w * 4 + r;
#pragma unroll
        for (int b = 0; b < 8; b++)
            acc[b] = fmaf(sh[row][b], wpre[r], acc[b]);
    }
#pragma unroll
    for (int b = 0; b < 8; b++)
        sred[w][lane * 8 + b] = acc[b];
    __syncthreads();

    int lane_o = t >> 3;
    int b_o    = t & 7;
    float tot = sred[0][lane_o * 8 + b_o];
#pragma unroll
    for (int x = 1; x < 8; x++)
        tot += sred[x][lane_o * 8 + b_o];
    atomicAdd(&g_h2s[b_o * H2 + j0 + lane_o], tot);
    cudaTriggerProgrammaticLaunchCompletion();
}

// ---------------- K5: BN2+ReLU -> GEMM3 -> BN+ReLU -> head -> logits ---------
__global__ void k_final(const float* __restrict__ b2,
                        const float* __restrict__ g2,
                        const float* __restrict__ be2,
                        const float* __restrict__ W3,
                        const float* __restrict__ b3,
                        const float* __restrict__ g3,
                        const float* __restrict__ be3,
                        const float* __restrict__ Wh1,
                        const float* __restrict__ bh1,
                        const float* __restrict__ gh,
                        const float* __restrict__ beh,
                        const float* __restrict__ Wh2,
                        const float* __restrict__ bh2,
                        float* __restrict__ out) {
    __shared__ float sh2[B_ * H2];                 // 8 KB
    __shared__ __align__(16) float sW3[H2 * H3];   // 16 KB
    __shared__ float spart[2][B_ * H3];
    __shared__ float sfeat[B_ * H3];
    int t = threadIdx.x;
    float sbn = rsqrtf(1.0f + BN_EPS);

    // prologue: W3 prefetch, independent of gemm2 output
    float4 w3r[4];
#pragma unroll
    for (int i = 0; i < 4; i++)
        w3r[i] = __ldg(reinterpret_cast<const float4*>(W3) + t * 4 + i);
#pragma unroll
    for (int i = 0; i < 4; i++)
        reinterpret_cast<float4*>(sW3)[t * 4 + i] = w3r[i];

    cudaGridDependencySynchronize();    // g_h2s ready

    // Stage A: BN2 + ReLU from summed h2 (vectorized)
#pragma unroll
    for (int it = 0; it < 2; it++) {
        int i4 = t + it * 256;      // float4 index, 512 total
        float4 v = *reinterpret_cast<const float4*>(g_h2s + i4 * 4);
        float r[4] = {v.x, v.y, v.z, v.w};
#pragma unroll
        for (int c = 0; c < 4; c++) {
            int j = (i4 * 4 + c) & (H2 - 1);
            r[c] = fmaxf((r[c] + b2[j]) * (g2[j] * sbn) + be2[j], 0.f);
        }
        *reinterpret_cast<float4*>(sh2 + i4 * 4) =
            make_float4(r[0], r[1], r[2], r[3]);
    }
    __syncthreads();

    // Stage B: 2-way k-split GEMM3 (W3 from shared)
    {
        int pair = t & 127;
        int half = t >> 7;
        int b = pair >> 4, j = pair & 15;
        float acc = 0.f;
        int kk0 = half * (H2 / 2);
        for (int k = kk0; k < kk0 + H2 / 2; k++)
            acc = fmaf(sh2[b * H2 + k], sW3[k * H3 + j], acc);
        spart[half][pair] = acc;
    }
    __syncthreads();
    if (t < B_ * H3) {
        int j = t & 15;
        float acc = spart[0][t] + spart[1][t];
        float v = (acc + b3[j]) * (g3[j] * sbn) + be3[j];
        sfeat[t] = fmaxf(v, 0.f);
    }
    __syncthreads();

    // Stage C: head
    if (t < B_) {
        int b = t;
        float logit = bh2[0];
#pragma unroll
        for (int q = 0; q < 4; q++) {
            float acc = bh1[q];
            for (int p = 0; p < 15; p++)
                acc = fmaf(sfeat[b * H3 + p], Wh1[p * 4 + q], acc);
            float m = fmaxf(acc * (gh[q] * sbn) + beh[q], 0.f);
            logit = fmaf(m, Wh2[q], logit);
        }
        out[b] = logit;
    }
    cudaTriggerProgrammaticLaunchCompletion();
}

// ---------------- PDL launch helper -------------------------------------------
template <typename F, typename... Args>
static void launch_pdl(F func, int grid, int block, Args... args) {
    cudaLaunchConfig_t cfg = {};
    cfg.gridDim  = dim3(grid, 1, 1);
    cfg.blockDim = dim3(block, 1, 1);
    cfg.stream   = 0;
    cudaLaunchAttribute attr[1];
    attr[0].id = cudaLaunchAttributeProgrammaticStreamSerialization;
    attr[0].val.programmaticStreamSerializationAllowed = 1;
    cfg.attrs = attr;
    cfg.numAttrs = 1;
    cudaLaunchKernelEx(&cfg, func, args...);
}

// ---------------- launch -----------------------------------------------------
extern "C" void kernel_launch(void* const* d_in, const int* in_sizes, int n_in,
                              void* d_out, int out_size) {
    const float* snp      = (const float*)d_in[0];
    const int*   snp_ids  = (const int*)  d_in[1];
    const int*   node_seg = (const int*)  d_in[2];
    const float* filters  = (const float*)d_in[3];
    const float* W1  = (const float*)d_in[4];
    const float* b1  = (const float*)d_in[5];
    const float* g1  = (const float*)d_in[6];
    const float* be1 = (const float*)d_in[7];
    const float* W2  = (const float*)d_in[8];
    const float* b2  = (const float*)d_in[9];
    const float* g2  = (const float*)d_in[10];
    const float* be2 = (const float*)d_in[11];
    const float* W3  = (const float*)d_in[12];
    const float* b3  = (const float*)d_in[13];
    const float* g3  = (const float*)d_in[14];
    const float* be3 = (const float*)d_in[15];
    const float* Wh1 = (const float*)d_in[16];
    const float* bh1 = (const float*)d_in[17];
    const float* gh  = (const float*)d_in[18];
    const float* beh = (const float*)d_in[19];
    const float* Wh2 = (const float*)d_in[20];
    const float* bh2 = (const float*)d_in[21];
    float* out = (float*)d_out;

    int segsum_blocks = (int)((NNODE + SEG_NODES - 1) / SEG_NODES);  // 1954
    launch_pdl(k_prep, SCALE_BLOCKS + ZERO_BLOCKS, 256, snp, filters);
    launch_pdl(k_segsum, segsum_blocks, 256, snp_ids, node_seg);
    launch_pdl(k_gemm1, G1_KSPLIT * 8, 256, W1);
    launch_pdl(k_gemm2, 256, 256, W2, b1, g1, be1);
    launch_pdl(k_final, 1, 256, b2, g2, be2, W3, b3, g3, be3,
               Wh1, bh1, gh, beh, Wh2, bh2, out);
}

// round 16
// speedup vs baseline: 1.0738x; 1.0302x over previous
#include <cuda_runtime.h>
#include <cuda_bf16.h>
#include <cuda_fp16.h>
#include <math.h>

#define B_      8
#define NSNP    500000
#define NNODE   2000000
#define NG      20000
#define NF      8
#define H1      1024
#define H2      256
#define H3      16
#define BN_EPS  1e-5f

#define G1_KSPLIT 50
#define G1_KCHUNK 400     // 50 * 400 = 20000

// ---------------- f32x2 packed helpers (Blackwell) ---------------------------
__device__ __forceinline__ unsigned long long pack_dup(float x) {
    unsigned long long r;
    asm("mov.b64 %0, {%1, %1};" : "=l"(r) : "f"(x));
    return r;
}
__device__ __forceinline__ void fma2(unsigned long long& d,
                                     unsigned long long a,
                                     unsigned long long b) {
    asm("fma.rn.f32x2 %0, %1, %2, %0;" : "+l"(d) : "l"(a), "l"(b));
}
__device__ __forceinline__ float2 unpack2(unsigned long long v) {
    float2 f;
    asm("mov.b64 {%0, %1}, %2;" : "=f"(f.x), "=f"(f.y) : "l"(v));
    return f;
}

// streaming (evict-first) loads for single-use inputs
__device__ __forceinline__ float4 ldcs4(const float4* p) { return __ldcs(p); }
__device__ __forceinline__ int4   ldcs4i(const int4* p)  { return __ldcs(p); }

// ---------------- scratch ----------------------------------------------------
// Zero-initialized at module load; every replay re-zeros them in k_final.
__device__ __half g_scaledh[NSNP * B_];          // [n][b]  8 MB (L2-resident)
__device__ float  g_sample[NG * B_];             // [g][b]  640 KB
__device__ float  g_h1s[B_ * H1];                // summed (pre-BN)
__device__ float  g_h2s[B_ * H2];                // summed (pre-BN)

// pack 8 floats -> 4 half2 -> one 16B store
__device__ __forceinline__ void store_node8(__half* dst,
                                            float a0, float a1, float a2,
                                            float a3, float a4, float a5,
                                            float a6, float a7) {
    __half2 h0 = __floats2half2_rn(a0, a1);
    __half2 h1 = __floats2half2_rn(a2, a3);
    __half2 h2 = __floats2half2_rn(a4, a5);
    __half2 h3 = __floats2half2_rn(a6, a7);
    uint4 u;
    u.x = *reinterpret_cast<unsigned*>(&h0);
    u.y = *reinterpret_cast<unsigned*>(&h1);
    u.z = *reinterpret_cast<unsigned*>(&h2);
    u.w = *reinterpret_cast<unsigned*>(&h3);
    *reinterpret_cast<uint4*>(dst) = u;
}

// ---------------- K1: pure streaming scale (loads hoisted above gridsync) ----
#define SCALE_BLOCKS ((NSNP / 4 + 255) / 256)                          // 489
__global__ void k_prep(const float* __restrict__ snp,
                       const float* __restrict__ filters) {
    int q = blockIdx.x * blockDim.x + threadIdx.x;   // float4 index over n
    bool active = (q < NSNP / 4);
    float4 s = make_float4(0.f, 0.f, 0.f, 0.f);
    float4 sv[NF];
    if (active) {
        // inputs are never written by any kernel -> safe before gridsync;
        // overlaps the previous replay's tail under PDL.
#pragma unroll
        for (int f = 0; f < NF; f++) {
            float4 v = ldcs4(reinterpret_cast<const float4*>(filters) +
                             (size_t)f * (NSNP / 4) + q);
            s.x += v.x; s.y += v.y; s.z += v.z; s.w += v.w;
        }
#pragma unroll
        for (int b = 0; b < NF; b++)
            sv[b] = ldcs4(reinterpret_cast<const float4*>(snp) +
                          (size_t)b * (NSNP / 4) + q);
    }

    // stores to g_scaledh must wait: previous replay's segsum reads it
    cudaGridDependencySynchronize();

    if (!active) { cudaTriggerProgrammaticLaunchCompletion(); return; }
    const float inv = 1.0f / NF;
    s.x *= inv; s.y *= inv; s.z *= inv; s.w *= inv;

    int n0 = q * 4;
    __half* o = g_scaledh + (size_t)n0 * 8;
    store_node8(o,      sv[0].x * s.x, sv[1].x * s.x, sv[2].x * s.x, sv[3].x * s.x,
                        sv[4].x * s.x, sv[5].x * s.x, sv[6].x * s.x, sv[7].x * s.x);
    store_node8(o + 8,  sv[0].y * s.y, sv[1].y * s.y, sv[2].y * s.y, sv[3].y * s.y,
                        sv[4].y * s.y, sv[5].y * s.y, sv[6].y * s.y, sv[7].y * s.y);
    store_node8(o + 16, sv[0].z * s.z, sv[1].z * s.z, sv[2].z * s.z, sv[3].z * s.z,
                        sv[4].z * s.z, sv[5].z * s.z, sv[6].z * s.z, sv[7].z * s.z);
    store_node8(o + 24, sv[0].w * s.w, sv[1].w * s.w, sv[2].w * s.w, sv[3].w * s.w,
                        sv[4].w * s.w, sv[5].w * s.w, sv[6].w * s.w, sv[7].w * s.w);
    cudaTriggerProgrammaticLaunchCompletion();
}

// ---------------- K2: segmented sum, fp16 gathers, 32 nodes per subgroup -----
#define NODES_PER_SUB 32
#define SEG_NODES 1024      // 2,000,000 % 1024 = 128 (multiple of 128)
__global__ void k_segsum(const int* __restrict__ ids,
                         const int* __restrict__ seg) {
    __shared__ int sids[SEG_NODES];
    __shared__ int sseg[SEG_NODES];
    int t = threadIdx.x;
    long blockBase = (long)blockIdx.x * SEG_NODES;
    long rem = NNODE - blockBase;       // multiple of 128

    // prologue: index staging is independent of k_prep -> overlaps via PDL
    if (t * 4 < rem)
        reinterpret_cast<int4*>(sids)[t] =
            ldcs4i(reinterpret_cast<const int4*>(ids + blockBase) + t);
    if (t * 4 < rem)
        reinterpret_cast<int4*>(sseg)[t] =
            ldcs4i(reinterpret_cast<const int4*>(seg + blockBase) + t);
    __syncthreads();

    cudaGridDependencySynchronize();    // g_scaledh ready (g_sample pre-zeroed)

    int w    = t >> 5;
    int lane = t & 31;
    int sub  = lane >> 3;
    int b    = lane & 7;
    int nb   = w * 128 + sub * NODES_PER_SUB;
    if (w * 128 >= rem) { cudaTriggerProgrammaticLaunchCompletion(); return; }

    float v[NODES_PER_SUB];
#pragma unroll
    for (int k = 0; k < NODES_PER_SUB; k++)
        v[k] = __half2float(
            __ldg(g_scaledh + (size_t)sids[nb + k] * 8 + b));

    int cur = sseg[nb];
    float acc = 0.f;
#pragma unroll
    for (int k = 0; k < NODES_PER_SUB; k++) {
        int sgk = sseg[nb + k];
        if (sgk != cur) {
            atomicAdd(&g_sample[(size_t)cur * 8 + b], acc);
            acc = 0.f;
            cur = sgk;
        }
        acc += v[k];
    }
    atomicAdd(&g_sample[(size_t)cur * 8 + b], acc);
    cudaTriggerProgrammaticLaunchCompletion();
}

// ---------------- K3: GEMM1 direct (best shape) + early W1 prefetch ----------
// grid = 50 k-splits x 8 j-tiles(128 cols). 8 warps; warp w strides k rows
// {w, w+8, ...} (50 rows); lane owns 4 consecutive cols (LDG.128 of W).
__global__ void k_gemm1(const float* __restrict__ W1) {
    __shared__ __align__(16) float ssamp[G1_KCHUNK][8];   // 12.8 KB
    __shared__ float4 sred[8][256];                        // 32 KB
    int bx = blockIdx.x;
    int jt = bx & 7;
    int k0 = (bx >> 3) * G1_KCHUNK;
    int t  = threadIdx.x;
    int w  = t >> 5;
    int lane = t & 31;
    int j0 = jt * 128;
    int j = j0 + lane * 4;

    // early W1 prefetch: inputs have no dependency, overlap the PDL wait
    float4 wpre0 = __ldg(reinterpret_cast<const float4*>(
        W1 + (size_t)(k0 + w) * H1 + j));
    float4 wpre1 = __ldg(reinterpret_cast<const float4*>(
        W1 + (size_t)(k0 + 8 + w) * H1 + j));

    cudaGridDependencySynchronize();    // g_sample ready

    for (int i = t; i < G1_KCHUNK * 2; i += 256)
        reinterpret_cast<float4*>(ssamp)[i] =
            __ldg(reinterpret_cast<const float4*>(g_sample) + k0 * 2 + i);
    __syncthreads();

    unsigned long long acc2[4][4];
#pragma unroll
    for (int bp = 0; bp < 4; bp++)
#pragma unroll
        for (int c = 0; c < 4; c++) acc2[bp][c] = 0ull;

#pragma unroll 5
    for (int r = 0; r < G1_KCHUNK / 8; r++) {
        int row = r * 8 + w;
        float4 wv;
        if (r == 0)      wv = wpre0;
        else if (r == 1) wv = wpre1;
        else             wv = __ldg(reinterpret_cast<const float4*>(
                                  W1 + (size_t)(k0 + row) * H1 + j));
        ulonglong2 p0 = *reinterpret_cast<const ulonglong2*>(&ssamp[row][0]);
        ulonglong2 p1 = *reinterpret_cast<const ulonglong2*>(&ssamp[row][4]);
        unsigned long long sv2[4] = {p0.x, p0.y, p1.x, p1.y};
        unsigned long long wd[4] = {pack_dup(wv.x), pack_dup(wv.y),
                                    pack_dup(wv.z), pack_dup(wv.w)};
#pragma unroll
        for (int bp = 0; bp < 4; bp++) {
            fma2(acc2[bp][0], sv2[bp], wd[0]);
            fma2(acc2[bp][1], sv2[bp], wd[1]);
            fma2(acc2[bp][2], sv2[bp], wd[2]);
            fma2(acc2[bp][3], sv2[bp], wd[3]);
        }
    }

#pragma unroll
    for (int bp = 0; bp < 4; bp++) {
        float2 c0 = unpack2(acc2[bp][0]);
        float2 c1 = unpack2(acc2[bp][1]);
        float2 c2 = unpack2(acc2[bp][2]);
        float2 c3 = unpack2(acc2[bp][3]);
        sred[w][lane * 8 + bp * 2 + 0] = make_float4(c0.x, c1.x, c2.x, c3.x);
        sred[w][lane * 8 + bp * 2 + 1] = make_float4(c0.y, c1.y, c2.y, c3.y);
    }
    __syncthreads();

    int lane_o = t >> 3;
    int b_o    = t & 7;
    float4 tot = sred[0][lane_o * 8 + b_o];
#pragma unroll
    for (int x = 1; x < 8; x++) {
        float4 v = sred[x][lane_o * 8 + b_o];
        tot.x += v.x; tot.y += v.y; tot.z += v.z; tot.w += v.w;
    }
    float* dst = g_h1s + b_o * H1 + j0 + lane_o * 4;
    atomicAdd(dst + 0, tot.x);
    atomicAdd(dst + 1, tot.y);
    atomicAdd(dst + 2, tot.z);
    atomicAdd(dst + 3, tot.w);
    cudaTriggerProgrammaticLaunchCompletion();
}

// ---------------- K4: GEMM2 direct, W2 prefetched (PDL prologue) -------------
__global__ void k_gemm2(const float* __restrict__ W2,
                        const float* __restrict__ b1,
                        const float* __restrict__ g1,
                        const float* __restrict__ be1) {
    __shared__ float sh[32][8];         // BN1(h1) for this k-chunk
    __shared__ float sred[8][32 * 8];   // per-warp partials
    int bx = blockIdx.x;
    int js = bx & 7;
    int ks = bx >> 3;
    int k0 = ks * 32;
    int j0 = js * 32;
    int t  = threadIdx.x;
    int w  = t >> 5;
    int lane = t & 31;

    // prologue: W2 + BN params, independent of gemm1 output
    float wpre[4];
#pragma unroll
    for (int r = 0; r < 4; r++)
        wpre[r] = __ldg(W2 + (size_t)(k0 + w * 4 + r) * H2 + j0 + lane);
    int kk = k0 + (t >> 3);
    float sc  = g1[kk] * rsqrtf(1.0f + BN_EPS);
    float bb1 = b1[kk];
    float bbe = be1[kk];

    cudaGridDependencySynchronize();    // g_h1s ready

    {
        int b = t & 7;
        float v = (g_h1s[b * H1 + kk] + bb1) * sc + bbe;
        sh[t >> 3][b] = fmaxf(v, 0.f);
    }
    __syncthreads();

    float acc[8];
#pragma unroll
    for (int b = 0; b < 8; b++) acc[b] = 0.f;
#pragma unroll
    for (int r = 0; r < 4; r++) {
        int row = w * 4 + r;
#pragma unroll
        for (int b = 0; b < 8; b++)
            acc[b] = fmaf(sh[row][b], wpre[r], acc[b]);
    }
#pragma unroll
    for (int b = 0; b < 8; b++)
        sred[w][lane * 8 + b] = acc[b];
    __syncthreads();

    int lane_o = t >> 3;
    int b_o    = t & 7;
    float tot = sred[0][lane_o * 8 + b_o];
#pragma unroll
    for (int x = 1; x < 8; x++)
        tot += sred[x][lane_o * 8 + b_o];
    atomicAdd(&g_h2s[b_o * H2 + j0 + lane_o], tot);
    cudaTriggerProgrammaticLaunchCompletion();
}

// ---------------- K5: final pipeline (block 0) + accumulator re-zero ---------
#define FINAL_BLOCKS 48
__global__ void k_final(const float* __restrict__ b2,
                        const float* __restrict__ g2,
                        const float* __restrict__ be2,
                        const float* __restrict__ W3,
                        const float* __restrict__ b3,
                        const float* __restrict__ g3,
                        const float* __restrict__ be3,
                        const float* __restrict__ Wh1,
                        const float* __restrict__ bh1,
                        const float* __restrict__ gh,
                        const float* __restrict__ beh,
                        const float* __restrict__ Wh2,
                        const float* __restrict__ bh2,
                        float* __restrict__ out) {
    int t = threadIdx.x;

    if (blockIdx.x != 0) {
        // zero g_sample + g_h1s for the next replay; gemm1/gemm2 are done
        // reading them (transitively guaranteed by this grid's PDL gridsync).
        cudaGridDependencySynchronize();
        const int n0 = NG * B_ / 4;                 // 40000 float4
        const int n1 = n0 + B_ * H1 / 4;            // +2048
        int idx = (blockIdx.x - 1) * 256 + t;
        int stride = (FINAL_BLOCKS - 1) * 256;      // 12032
        for (int i = idx; i < n1; i += stride) {
            if (i < n0)
                reinterpret_cast<float4*>(g_sample)[i] =
                    make_float4(0.f, 0.f, 0.f, 0.f);
            else
                reinterpret_cast<float4*>(g_h1s)[i - n0] =
                    make_float4(0.f, 0.f, 0.f, 0.f);
        }
        cudaTriggerProgrammaticLaunchCompletion();
        return;
    }

    __shared__ float sh2[B_ * H2];                 // 8 KB
    __shared__ __align__(16) float sW3[H2 * H3];   // 16 KB
    __shared__ float spart[2][B_ * H3];
    __shared__ float sfeat[B_ * H3];
    float sbn = rsqrtf(1.0f + BN_EPS);

    // prologue: W3 prefetch, independent of gemm2 output
    float4 w3r[4];
#pragma unroll
    for (int i = 0; i < 4; i++)
        w3r[i] = __ldg(reinterpret_cast<const float4*>(W3) + t * 4 + i);
#pragma unroll
    for (int i = 0; i < 4; i++)
        reinterpret_cast<float4*>(sW3)[t * 4 + i] = w3r[i];

    cudaGridDependencySynchronize();    // g_h2s ready

    // Stage A: BN2 + ReLU from summed h2 (vectorized), then re-zero g_h2s
#pragma unroll
    for (int it = 0; it < 2; it++) {
        int i4 = t + it * 256;      // float4 index, 512 total
        float4 v = *reinterpret_cast<const float4*>(g_h2s + i4 * 4);
        float r[4] = {v.x, v.y, v.z, v.w};
#pragma unroll
        for (int c = 0; c < 4; c++) {
            int j = (i4 * 4 + c) & (H2 - 1);
            r[c] = fmaxf((r[c] + b2[j]) * (g2[j] * sbn) + be2[j], 0.f);
        }
        *reinterpret_cast<float4*>(sh2 + i4 * 4) =
            make_float4(r[0], r[1], r[2], r[3]);
        *reinterpret_cast<float4*>(g_h2s + i4 * 4) =
            make_float4(0.f, 0.f, 0.f, 0.f);
    }
    __syncthreads();

    // Stage B: 2-way k-split GEMM3 (W3 from shared)
    {
        int pair = t & 127;
        int half = t >> 7;
        int b = pair >> 4, j = pair & 15;
        float acc = 0.f;
        int kk0 = half * (H2 / 2);
        for (int k = kk0; k < kk0 + H2 / 2; k++)
            acc = fmaf(sh2[b * H2 + k], sW3[k * H3 + j], acc);
        spart[half][pair] = acc;
    }
    __syncthreads();
    if (t < B_ * H3) {
        int j = t & 15;
        float acc = spart[0][t] + spart[1][t];
        float v = (acc + b3[j]) * (g3[j] * sbn) + be3[j];
        sfeat[t] = fmaxf(v, 0.f);
    }
    __syncthreads();

    // Stage C: head
    if (t < B_) {
        int b = t;
        float logit = bh2[0];
#pragma unroll
        for (int q = 0; q < 4; q++) {
            float acc = bh1[q];
            for (int p = 0; p < 15; p++)
                acc = fmaf(sfeat[b * H3 + p], Wh1[p * 4 + q], acc);
            float m = fmaxf(acc * (gh[q] * sbn) + beh[q], 0.f);
            logit = fmaf(m, Wh2[q], logit);
        }
        out[b] = logit;
    }
    cudaTriggerProgrammaticLaunchCompletion();
}

// ---------------- PDL launch helper -------------------------------------------
template <typename F, typename... Args>
static void launch_pdl(F func, int grid, int block, Args... args) {
    cudaLaunchConfig_t cfg = {};
    cfg.gridDim  = dim3(grid, 1, 1);
    cfg.blockDim = dim3(block, 1, 1);
    cfg.stream   = 0;
    cudaLaunchAttribute attr[1];
    attr[0].id = cudaLaunchAttributeProgrammaticStreamSerialization;
    attr[0].val.programmaticStreamSerializationAllowed = 1;
    cfg.attrs = attr;
    cfg.numAttrs = 1;
    cudaLaunchKernelEx(&cfg, func, args...);
}

// ---------------- launch -----------------------------------------------------
extern "C" void kernel_launch(void* const* d_in, const int* in_sizes, int n_in,
                              void* d_out, int out_size) {
    const float* snp      = (const float*)d_in[0];
    const int*   snp_ids  = (const int*)  d_in[1];
    const int*   node_seg = (const int*)  d_in[2];
    const float* filters  = (const float*)d_in[3];
    const float* W1  = (const float*)d_in[4];
    const float* b1  = (const float*)d_in[5];
    const float* g1  = (const float*)d_in[6];
    const float* be1 = (const float*)d_in[7];
    const float* W2  = (const float*)d_in[8];
    const float* b2  = (const float*)d_in[9];
    const float* g2  = (const float*)d_in[10];
    const float* be2 = (const float*)d_in[11];
    const float* W3  = (const float*)d_in[12];
    const float* b3  = (const float*)d_in[13];
    const float* g3  = (const float*)d_in[14];
    const float* be3 = (const float*)d_in[15];
    const float* Wh1 = (const float*)d_in[16];
    const float* bh1 = (const float*)d_in[17];
    const float* gh  = (const float*)d_in[18];
    const float* beh = (const float*)d_in[19];
    const float* Wh2 = (const float*)d_in[20];
    const float* bh2 = (const float*)d_in[21];
    float* out = (float*)d_out;

    int segsum_blocks = (int)((NNODE + SEG_NODES - 1) / SEG_NODES);  // 1954
    launch_pdl(k_prep, SCALE_BLOCKS, 256, snp, filters);
    launch_pdl(k_segsum, segsum_blocks, 256, snp_ids, node_seg);
    launch_pdl(k_gemm1, G1_KSPLIT * 8, 256, W1);
    launch_pdl(k_gemm2, 256, 256, W2, b1, g1, be1);
    launch_pdl(k_final, FINAL_BLOCKS, 256, b2, g2, be2, W3, b3, g3, be3,
               Wh1, bh1, gh, beh, Wh2, bh2, out);
}